// round 10
// baseline (speedup 1.0000x reference)
#include <cuda_runtime.h>
#include <cuda_bf16.h>
#include <cstdint>

#define BB 64
#define TT 512
#define DD 1024
#define LL 32
#define CH 16    // chunks per sequence
#define CL 32    // steps per chunk

__device__ float g_q[BB * TT * LL];          // 4 MB: exp(emissions)
__device__ float g_cm[BB * CH * LL * LL];    // 4 MB: chunk product matrices
__device__ float g_cex[BB * CH];             // chunk log-scales
__device__ float g_nll[BB];
__device__ unsigned g_done;

// ---------------------------------------------------------------------------
// helpers
// ---------------------------------------------------------------------------
__device__ __forceinline__ uint32_t rna(float x) {   // unbiased round to tf32
    uint32_t r;
    asm("cvt.rna.tf32.f32 %0, %1;" : "=r"(r) : "f"(x));
    return r;
}
__device__ __forceinline__ void mma_tf32(float* c,
                                         uint32_t a0, uint32_t a1,
                                         uint32_t a2, uint32_t a3,
                                         uint32_t b0, uint32_t b1) {
    asm volatile(
        "mma.sync.aligned.m16n8k8.row.col.f32.tf32.tf32.f32 "
        "{%0,%1,%2,%3}, {%4,%5,%6,%7}, {%8,%9}, {%0,%1,%2,%3};"
        : "+f"(c[0]), "+f"(c[1]), "+f"(c[2]), "+f"(c[3])
        : "r"(a0), "r"(a1), "r"(a2), "r"(a3), "r"(b0), "r"(b1));
}
__device__ __forceinline__ void mma_bf16(float* c,
                                         uint32_t a0, uint32_t a1,
                                         uint32_t a2, uint32_t a3,
                                         uint32_t b0, uint32_t b1) {
    asm volatile(
        "mma.sync.aligned.m16n8k16.row.col.f32.bf16.bf16.f32 "
        "{%0,%1,%2,%3}, {%4,%5,%6,%7}, {%8,%9}, {%0,%1,%2,%3};"
        : "+f"(c[0]), "+f"(c[1]), "+f"(c[2]), "+f"(c[3])
        : "r"(a0), "r"(a1), "r"(a2), "r"(a3), "r"(b0), "r"(b1));
}
__device__ __forceinline__ uint32_t bf2pack(float hi, float lo) {
    uint32_t r;
    asm("cvt.rn.bf16x2.f32 %0, %1, %2;" : "=r"(r) : "f"(hi), "f"(lo));
    return r;
}

// ---------------------------------------------------------------------------
// Kernel 1 (fused): emissions GEMM (tf32 mma, cp.async pipeline) + chunk
// matrix products (bf16 mma) on the block's own 64 rows = 2 chunks.
//
// dynamic smem layout (bytes):
//   [0, 36864)      As[4][64*APD] f32 (GEMM stage buffers)
//     -- reused by chunk phase (stages dead after mainloop):
//     [0, 8192)       qs [64][32] f32
//     [8192, 10752)   Eb bf16 [32][SPB]
//     [10752, 15872)  Cs bf16 [2][32][SPB]
//     [15872, 15904)  scl[8] f32
//   [36864, 46080)  Ws[2][32*APD] u32 (tf32 bits)
//   [46080, 46208)  bs[32] f32
// ---------------------------------------------------------------------------
#define NSTG 4
#define APD  36
#define NT   (DD / 32)
#define SPB  40
#define SM_TOTAL 46208

__global__ void __launch_bounds__(128) emis_fused(const float* __restrict__ A,
                                                  const float* __restrict__ W,
                                                  const float* __restrict__ bias,
                                                  const float* __restrict__ trans) {
    extern __shared__ __align__(16) char smraw[];
    float*    As = (float*)smraw;
    uint32_t* Ws = (uint32_t*)(smraw + 36864);
    float*    bs = (float*)(smraw + 46080);
    // chunk-phase aliases (valid only after GEMM mainloop)
    float*         qs  = (float*)smraw;                       // [64][32]
    __nv_bfloat16* Eb  = (__nv_bfloat16*)(smraw + 8192);      // [32][SPB]
    __nv_bfloat16* Cs  = (__nv_bfloat16*)(smraw + 10752);     // [2][32][SPB]
    float*         scl = (float*)(smraw + 15872);             // [8]

    const int t    = threadIdx.x;
    const int w    = t >> 5;
    const int lane = t & 31;
    const int g    = lane >> 2;
    const int tig  = lane & 3;
    const int row0 = blockIdx.x * 64;

    if (blockIdx.x == 0 && t == 0) g_done = 0;   // fused-finalize counter reset
    if (t < LL) bs[t] = bias[t];

    // ------------------ GEMM phase (proven R9 pipeline) ------------------
    auto a_issue = [&](int tile) {
        const int s = tile & (NSTG - 1);
        const int k0 = tile * 32;
#pragma unroll
        for (int i = 0; i < 4; ++i) {
            int idx = t + 128 * i;
            int m = idx >> 3, kq = idx & 7;
            uint32_t dst = (uint32_t)__cvta_generic_to_shared(
                &As[s * 64 * APD + m * APD + kq * 4]);
            const float* src = A + (size_t)(row0 + m) * DD + k0 + kq * 4;
            asm volatile("cp.async.cg.shared.global [%0], [%1], 16;"
                         :: "r"(dst), "l"(src));
        }
        asm volatile("cp.async.commit_group;" ::: "memory");
    };

    float4 wR[2];
    auto w_ldg = [&](int tile) {
        const int k0 = tile * 32;
#pragma unroll
        for (int i = 0; i < 2; ++i) {
            int idx = t + 128 * i;
            int n = idx >> 3, kq = idx & 7;
            wR[i] = *(const float4*)(W + (size_t)n * DD + k0 + kq * 4);
        }
    };
    auto w_sts = [&](int buf) {
#pragma unroll
        for (int i = 0; i < 2; ++i) {
            int idx = t + 128 * i;
            int n = idx >> 3, kq = idx & 7;
            uint4 u;
            u.x = rna(wR[i].x); u.y = rna(wR[i].y);
            u.z = rna(wR[i].z); u.w = rna(wR[i].w);
            *(uint4*)&Ws[buf * LL * APD + n * APD + kq * 4] = u;
        }
    };

    a_issue(0); a_issue(1); a_issue(2);
    w_ldg(0); w_sts(0); w_ldg(1);

    float acc[4][4];
#pragma unroll
    for (int nf = 0; nf < 4; ++nf)
#pragma unroll
        for (int i = 0; i < 4; ++i) acc[nf][i] = 0.0f;

    const int rA0 = (16 * w + g) * APD;
    const int rA1 = (16 * w + g + 8) * APD;

    for (int it = 0; it < NT; ++it) {
        if (it <= NT - 3)
            asm volatile("cp.async.wait_group 2;" ::: "memory");
        else if (it == NT - 2)
            asm volatile("cp.async.wait_group 1;" ::: "memory");
        else
            asm volatile("cp.async.wait_group 0;" ::: "memory");
        __syncthreads();

        const float*    as = As + (it & (NSTG - 1)) * 64 * APD;
        const uint32_t* ws = Ws + (it & 1) * LL * APD;
#pragma unroll
        for (int ks = 0; ks < 4; ++ks) {
            const int k = 8 * ks;
            uint32_t a0 = __float_as_uint(as[rA0 + k + tig]);
            uint32_t a1 = __float_as_uint(as[rA1 + k + tig]);
            uint32_t a2 = __float_as_uint(as[rA0 + k + tig + 4]);
            uint32_t a3 = __float_as_uint(as[rA1 + k + tig + 4]);
#pragma unroll
            for (int nf = 0; nf < 4; ++nf) {
                uint32_t b0 = ws[(8 * nf + g) * APD + k + tig];
                uint32_t b1 = ws[(8 * nf + g) * APD + k + tig + 4];
                mma_tf32(acc[nf], a0, a1, a2, a3, b0, b1);
            }
        }
        if (it + 1 < NT) {
            w_sts((it + 1) & 1);
            if (it + 2 < NT) w_ldg(it + 2);
            if (it + 3 < NT) a_issue(it + 3);
        }
    }

    // ---- epilogue: q = exp(acc + bias) -> g_q and qs (smem, reused As) ----
    // (stage 0 region overwritten; last mainloop iteration reads stage 3 only)
    const int r0l = 16 * w + g;                 // local row
    const int r0 = row0 + r0l;
#pragma unroll
    for (int nf = 0; nf < 4; ++nf) {
        const int n = nf * 8 + 2 * tig;
        float b0 = bs[n], b1 = bs[n + 1];
        float2 v0, v1;
        v0.x = __expf(acc[nf][0] + b0);
        v0.y = __expf(acc[nf][1] + b1);
        v1.x = __expf(acc[nf][2] + b0);
        v1.y = __expf(acc[nf][3] + b1);
        *(float2*)&g_q[(size_t)r0 * LL + n]       = v0;
        *(float2*)&g_q[(size_t)(r0 + 8) * LL + n] = v1;
        *(float2*)&qs[r0l * 32 + n]       = v0;
        *(float2*)&qs[(r0l + 8) * 32 + n] = v1;
    }
    // Eb[n][k] = bf16(exp(trans[k][n]))
    {
        const int n = t & 31, kb = (t >> 5) * 8;
#pragma unroll
        for (int i = 0; i < 8; ++i) {
            int k = kb + i;
            Eb[n * SPB + k] = __float2bfloat16(__expf(trans[k * 32 + n]));
        }
    }
    __syncthreads();

    // ------------------ chunk phase: 2 chunks x 2 warp-halves ------------------
    const int ch = w >> 1;                       // chunk within block (0,1)
    const int h  = w & 1;                        // 16-row half
    const int cglob = 2 * (blockIdx.x & 7) + ch; // chunk index in sequence
    const int b = blockIdx.x >> 3;
    const int ls0 = (cglob == 0) ? 1 : 0;

    __nv_bfloat16* Cc = Cs + ch * 32 * SPB;
    const float* qch = qs + ch * 32 * 32;        // [CL][32]

    // pinned B fragments of E
    uint32_t Bf[2][4][2];
#pragma unroll
    for (int kc = 0; kc < 2; ++kc)
#pragma unroll
        for (int nt = 0; nt < 4; ++nt) {
            Bf[kc][nt][0] = *(const uint32_t*)&Eb[(8 * nt + g) * SPB + 16 * kc + 2 * tig];
            Bf[kc][nt][1] = *(const uint32_t*)&Eb[(8 * nt + g) * SPB + 16 * kc + 2 * tig + 8];
        }

    // init my 16 rows: X[m][j] = E[m][j] * q[ls0][j]
#pragma unroll
    for (int r = 0; r < 16; ++r) {
        int m = 16 * h + r;
        Cc[m * SPB + lane] = __float2bfloat16(
            __bfloat162float(Eb[lane * SPB + m]) * qch[ls0 * 32 + lane]);
    }
    __syncwarp();

    float xac[4][4];
    float logC = 0.0f;
    const unsigned FULL = 0xffffffffu;

    for (int ls = ls0 + 1; ls < CL; ++ls) {
        uint32_t Af[2][4];
#pragma unroll
        for (int kc = 0; kc < 2; ++kc) {
            const int b0i = (16 * h + g) * SPB + 16 * kc + 2 * tig;
            const int b1i = (16 * h + g + 8) * SPB + 16 * kc + 2 * tig;
            Af[kc][0] = *(const uint32_t*)&Cc[b0i];
            Af[kc][1] = *(const uint32_t*)&Cc[b1i];
            Af[kc][2] = *(const uint32_t*)&Cc[b0i + 8];
            Af[kc][3] = *(const uint32_t*)&Cc[b1i + 8];
        }
#pragma unroll
        for (int nt = 0; nt < 4; ++nt)
#pragma unroll
            for (int v = 0; v < 4; ++v) xac[nt][v] = 0.0f;
#pragma unroll
        for (int kc = 0; kc < 2; ++kc)
#pragma unroll
            for (int nt = 0; nt < 4; ++nt)
                mma_bf16(xac[nt], Af[kc][0], Af[kc][1], Af[kc][2], Af[kc][3],
                         Bf[kc][nt][0], Bf[kc][nt][1]);

        // column scale by q_ls
#pragma unroll
        for (int nt = 0; nt < 4; ++nt) {
            float2 qv = *(const float2*)&qch[ls * 32 + 8 * nt + 2 * tig];
            xac[nt][0] *= qv.x; xac[nt][1] *= qv.y;
            xac[nt][2] *= qv.x; xac[nt][3] *= qv.y;
        }

        // per-half renorm every 8 steps (not the final step)
        if ((ls & 7) == 7 && ls != CL - 1) {
            float m = xac[0][0];
#pragma unroll
            for (int nt = 0; nt < 4; ++nt)
#pragma unroll
                for (int v = 0; v < 4; ++v) m = fmaxf(m, xac[nt][v]);
#pragma unroll
            for (int o = 16; o; o >>= 1) m = fmaxf(m, __shfl_xor_sync(FULL, m, o));
            float rinv;
            asm("rcp.approx.f32 %0, %1;" : "=f"(rinv) : "f"(m));
            logC += __logf(m);
#pragma unroll
            for (int nt = 0; nt < 4; ++nt)
#pragma unroll
                for (int v = 0; v < 4; ++v) xac[nt][v] *= rinv;
        }

        // pack & store back
#pragma unroll
        for (int nt = 0; nt < 4; ++nt) {
            uint32_t u01 = bf2pack(xac[nt][1], xac[nt][0]);
            uint32_t u23 = bf2pack(xac[nt][3], xac[nt][2]);
            *(uint32_t*)&Cc[(16 * h + g) * SPB + 8 * nt + 2 * tig]     = u01;
            *(uint32_t*)&Cc[(16 * h + g + 8) * SPB + 8 * nt + 2 * tig] = u23;
        }
        __syncwarp();
    }

    // ---- unify the two halves' scales; write g_cm / g_cex ----
    {
        float m = xac[0][0];
#pragma unroll
        for (int nt = 0; nt < 4; ++nt)
#pragma unroll
            for (int v = 0; v < 4; ++v) m = fmaxf(m, xac[nt][v]);
#pragma unroll
        for (int o = 16; o; o >>= 1) m = fmaxf(m, __shfl_xor_sync(FULL, m, o));
        float lw = logC + __logf(m);
        if (lane == 0) scl[w] = lw;
    }
    __syncthreads();
    {
        float L = fmaxf(scl[2 * ch], scl[2 * ch + 1]);
        float factor = __expf(logC - L);
#pragma unroll
        for (int nt = 0; nt < 4; ++nt) {
            uint32_t u01 = bf2pack(xac[nt][1] * factor, xac[nt][0] * factor);
            uint32_t u23 = bf2pack(xac[nt][3] * factor, xac[nt][2] * factor);
            *(uint32_t*)&Cc[(16 * h + g) * SPB + 8 * nt + 2 * tig]     = u01;
            *(uint32_t*)&Cc[(16 * h + g + 8) * SPB + 8 * nt + 2 * tig] = u23;
        }
        if (h == 0 && lane == 0) g_cex[b * CH + cglob] = L;
    }
    __syncthreads();

    // cooperative writeout: stored[r][i] = X[i][r]
    {
        float* out0 = g_cm + ((size_t)b * CH + 2 * (blockIdx.x & 7)) * (LL * LL);
        for (int idx = t; idx < 2 * LL * LL; idx += 128) {
            int c2 = idx >> 10, rem = idx & 1023;
            int r = rem >> 5, i = rem & 31;
            out0[c2 * (LL * LL) + r * 32 + i] =
                __bfloat162float(Cs[c2 * 32 * SPB + i * SPB + r]);
        }
    }
}

// ---------------------------------------------------------------------------
// Kernel 2: per-sequence combine + fused finalize (proven R9 version).
// ---------------------------------------------------------------------------
#define CMP 33
#define CMB_FLOATS (CH * LL * CMP + LL * LL + TT + 8)
#define CMB_SMEM   (CMB_FLOATS * 4)

__global__ void __launch_bounds__(128) crf_combine(const float* __restrict__ start_t,
                                                   const float* __restrict__ end_t,
                                                   const float* __restrict__ trans,
                                                   const int* __restrict__ labels,
                                                   float* __restrict__ out) {
    extern __shared__ __align__(16) float smf[];
    float* Cm = smf;
    float* Ts = Cm + CH * LL * CMP;
    int*   Ls = (int*)(Ts + LL * LL);
    float* res = (float*)(Ls + TT);
    __shared__ bool amLast;

    const int b = blockIdx.x;
    const int t = threadIdx.x;
    const int w = t >> 5;
    const int j = t & 31;
    const unsigned FULL = 0xffffffffu;

    {
        const float* src = g_cm + (size_t)b * CH * LL * LL;
        for (int idx = t; idx < CH * LL * LL; idx += 128) {
            int cc = idx >> 10, rem = idx & 1023;
            int r = rem >> 5, col = rem & 31;
            Cm[cc * (LL * CMP) + r * CMP + col] = src[idx];
        }
        ((float4*)Ts)[t]       = ((const float4*)trans)[t];
        ((float4*)Ts)[t + 128] = ((const float4*)trans)[t + 128];
        ((int4*)Ls)[t] = ((const int4*)(labels + b * TT))[t];
    }
    __syncthreads();

    if (w == 0) {
        const float Eend = __expf(end_t[j]);
        float p = __expf(start_t[j]) * g_q[(size_t)b * TT * LL + j];

        float logC = (j < CH) ? g_cex[b * CH + j] : 0.0f;
#pragma unroll
        for (int o = 16; o; o >>= 1) logC += __shfl_xor_sync(FULL, logC, o);

#pragma unroll 1
        for (int c = 0; c < CH; ++c) {
            const float* Cc = Cm + c * (LL * CMP) + j * CMP;
            float s0 = 0.f, s1 = 0.f, s2 = 0.f, s3 = 0.f;
#pragma unroll
            for (int i = 0; i < 32; i += 4) {
                float p0 = __shfl_sync(FULL, p, i + 0);
                float p1 = __shfl_sync(FULL, p, i + 1);
                float p2 = __shfl_sync(FULL, p, i + 2);
                float p3 = __shfl_sync(FULL, p, i + 3);
                s0 = fmaf(p0, Cc[i + 0], s0);
                s1 = fmaf(p1, Cc[i + 1], s1);
                s2 = fmaf(p2, Cc[i + 2], s2);
                s3 = fmaf(p3, Cc[i + 3], s3);
            }
            float pn = (s0 + s1) + (s2 + s3);
            float m = pn;
#pragma unroll
            for (int o = 16; o; o >>= 1) m = fmaxf(m, __shfl_xor_sync(FULL, m, o));
            float rinv;
            asm("rcp.approx.f32 %0, %1;" : "=f"(rinv) : "f"(m));
            logC += __logf(m);
            p = pn * rinv;
        }

        float v = p * Eend;
#pragma unroll
        for (int o = 16; o; o >>= 1) v += __shfl_xor_sync(FULL, v, o);
        if (j == 0) res[0] = logC + __logf(v);
    } else {
        float acc = 0.0f;
        const int gi = (w - 1) * 32 + j;
        for (int tt = 1 + gi; tt < TT; tt += 96) {
            int lp = Ls[tt - 1], lt = Ls[tt];
            acc += Ts[lp * LL + lt] + __logf(g_q[(size_t)b * TT * LL + tt * LL + lt]);
        }
#pragma unroll
        for (int o = 16; o; o >>= 1) acc += __shfl_xor_sync(FULL, acc, o);
        if (j == 0) res[w] = acc;
    }
    __syncthreads();

    if (t == 0) {
        int l0 = Ls[0], lT = Ls[TT - 1];
        float num = res[1] + res[2] + res[3]
                  + start_t[l0] + __logf(g_q[(size_t)b * TT * LL + l0])
                  + end_t[lT];
        g_nll[b] = res[0] - num;
        __threadfence();
        unsigned old = atomicAdd(&g_done, 1u);
        amLast = (old == BB - 1);
    }
    __syncthreads();

    if (amLast && w == 0) {
        __threadfence();
        float v = g_nll[j] + g_nll[j + 32];
#pragma unroll
        for (int o = 16; o; o >>= 1) v += __shfl_xor_sync(FULL, v, o);
        if (j == 0) out[0] = v * (1.0f / (float)BB);
    }
}

// ---------------------------------------------------------------------------
extern "C" void kernel_launch(void* const* d_in, const int* in_sizes, int n_in,
                              void* d_out, int out_size) {
    const float* emb    = (const float*)d_in[0];
    const float* W      = (const float*)d_in[1];
    const float* bias   = (const float*)d_in[2];
    const float* startt = (const float*)d_in[3];
    const float* endt   = (const float*)d_in[4];
    const float* trans  = (const float*)d_in[5];
    const int*   labels = (const int*)d_in[6];

    static int attr_set = 0;
    if (!attr_set) {
        cudaFuncSetAttribute(crf_combine, cudaFuncAttributeMaxDynamicSharedMemorySize,
                             CMB_SMEM);
        attr_set = 1;
    }

    emis_fused<<<(BB * TT) / 64, 128, SM_TOTAL>>>(emb, W, bias, trans);
    crf_combine<<<BB, 128, CMB_SMEM>>>(startt, endt, trans, labels, (float*)d_out);
}

// round 11
// speedup vs baseline: 1.1683x; 1.1683x over previous
#include <cuda_runtime.h>
#include <cuda_bf16.h>
#include <cstdint>

#define BB 64
#define TT 512
#define DD 1024
#define LL 32
#define CH 16    // chunks per sequence
#define CL 32    // steps per chunk

__device__ __align__(16) uint32_t g_cm[BB * CH * 512];  // 2 MB: chunk mats, bf16x2
__device__ float g_cex[BB * CH];             // chunk log-scales
__device__ float g_gold[BB * TT];            // log q[t, label_t]
__device__ float g_p0[BB * LL];              // q row 0 per sequence
__device__ float g_nll[BB];
__device__ unsigned g_done;

// ---------------------------------------------------------------------------
// helpers
// ---------------------------------------------------------------------------
__device__ __forceinline__ uint32_t rna(float x) {   // unbiased round to tf32
    uint32_t r;
    asm("cvt.rna.tf32.f32 %0, %1;" : "=r"(r) : "f"(x));
    return r;
}
__device__ __forceinline__ void mma_tf32(float* c,
                                         uint32_t a0, uint32_t a1,
                                         uint32_t a2, uint32_t a3,
                                         uint32_t b0, uint32_t b1) {
    asm volatile(
        "mma.sync.aligned.m16n8k8.row.col.f32.tf32.tf32.f32 "
        "{%0,%1,%2,%3}, {%4,%5,%6,%7}, {%8,%9}, {%0,%1,%2,%3};"
        : "+f"(c[0]), "+f"(c[1]), "+f"(c[2]), "+f"(c[3])
        : "r"(a0), "r"(a1), "r"(a2), "r"(a3), "r"(b0), "r"(b1));
}
__device__ __forceinline__ void mma_bf16(float* c,
                                         uint32_t a0, uint32_t a1,
                                         uint32_t a2, uint32_t a3,
                                         uint32_t b0, uint32_t b1) {
    asm volatile(
        "mma.sync.aligned.m16n8k16.row.col.f32.bf16.bf16.f32 "
        "{%0,%1,%2,%3}, {%4,%5,%6,%7}, {%8,%9}, {%0,%1,%2,%3};"
        : "+f"(c[0]), "+f"(c[1]), "+f"(c[2]), "+f"(c[3])
        : "r"(a0), "r"(a1), "r"(a2), "r"(a3), "r"(b0), "r"(b1));
}
__device__ __forceinline__ uint32_t bf2pack(float hi, float lo) {
    uint32_t r;
    asm("cvt.rn.bf16x2.f32 %0, %1, %2;" : "=r"(r) : "f"(hi), "f"(lo));
    return r;
}
__device__ __forceinline__ void fma2(unsigned long long& d, unsigned long long a,
                                     unsigned long long b) {
    asm("fma.rn.f32x2 %0, %1, %2, %0;" : "+l"(d) : "l"(a), "l"(b));
}
__device__ __forceinline__ unsigned long long add2(unsigned long long a,
                                                   unsigned long long b) {
    unsigned long long r;
    asm("add.rn.f32x2 %0, %1, %2;" : "=l"(r) : "l"(a), "l"(b));
    return r;
}
__device__ __forceinline__ unsigned long long pack2(float lo, float hi) {
    unsigned long long r;
    asm("mov.b64 %0, {%1, %2};" : "=l"(r) : "f"(lo), "f"(hi));
    return r;
}
__device__ __forceinline__ float2 unpack2(unsigned long long v) {
    float2 f;
    asm("mov.b64 {%0, %1}, %2;" : "=f"(f.x), "=f"(f.y) : "l"(v));
    return f;
}

// ---------------------------------------------------------------------------
// Kernel 1 (fused): emissions GEMM (tf32 mma, cp.async pipeline) + chunk
// matrix products (bf16 mma) on the block's own 64 rows = 2 chunks.
// No q written to global: only g_cm (bf16), g_cex, g_gold, g_p0.
//
// dynamic smem layout (bytes):
//   [0, 36864)      As[4][64*APD] f32 (GEMM stage buffers)
//     -- reused by chunk phase (stages dead after mainloop):
//     [0, 8192)       qs [64][32] f32
//     [8192, 10752)   Eb bf16 [32][SPB]
//     [10752, 15872)  Cs bf16 [2][32][SPB]
//     [15872, 15904)  scl[8] f32
//     [15904, 16160)  ls64[64] int
//   [36864, 46080)  Ws[2][32*APD] u32 (tf32 bits)
//   [46080, 46208)  bs[32] f32
// ---------------------------------------------------------------------------
#define NSTG 4
#define APD  36
#define NT   (DD / 32)
#define SPB  40
#define SM_TOTAL 46208

__global__ void __launch_bounds__(128) emis_fused(const float* __restrict__ A,
                                                  const float* __restrict__ W,
                                                  const float* __restrict__ bias,
                                                  const float* __restrict__ trans,
                                                  const int* __restrict__ labels) {
    extern __shared__ __align__(16) char smraw[];
    float*    As = (float*)smraw;
    uint32_t* Ws = (uint32_t*)(smraw + 36864);
    float*    bs = (float*)(smraw + 46080);
    // chunk-phase aliases (valid only after GEMM mainloop)
    float*         qs   = (float*)smraw;                      // [64][32]
    __nv_bfloat16* Eb   = (__nv_bfloat16*)(smraw + 8192);     // [32][SPB]
    __nv_bfloat16* Cs   = (__nv_bfloat16*)(smraw + 10752);    // [2][32][SPB]
    float*         scl  = (float*)(smraw + 15872);            // [8]
    int*           ls64 = (int*)(smraw + 15904);              // [64]

    const int t    = threadIdx.x;
    const int w    = t >> 5;
    const int lane = t & 31;
    const int g    = lane >> 2;
    const int tig  = lane & 3;
    const int row0 = blockIdx.x * 64;
    const int b    = blockIdx.x >> 3;
    const int blk8 = blockIdx.x & 7;

    if (blockIdx.x == 0 && t == 0) g_done = 0;   // fused-finalize counter reset
    if (t < LL) bs[t] = bias[t];

    // ------------------ GEMM phase (proven pipeline) ------------------
    auto a_issue = [&](int tile) {
        const int s = tile & (NSTG - 1);
        const int k0 = tile * 32;
#pragma unroll
        for (int i = 0; i < 4; ++i) {
            int idx = t + 128 * i;
            int m = idx >> 3, kq = idx & 7;
            uint32_t dst = (uint32_t)__cvta_generic_to_shared(
                &As[s * 64 * APD + m * APD + kq * 4]);
            const float* src = A + (size_t)(row0 + m) * DD + k0 + kq * 4;
            asm volatile("cp.async.cg.shared.global [%0], [%1], 16;"
                         :: "r"(dst), "l"(src));
        }
        asm volatile("cp.async.commit_group;" ::: "memory");
    };

    float4 wR[2];
    auto w_ldg = [&](int tile) {
        const int k0 = tile * 32;
#pragma unroll
        for (int i = 0; i < 2; ++i) {
            int idx = t + 128 * i;
            int n = idx >> 3, kq = idx & 7;
            wR[i] = *(const float4*)(W + (size_t)n * DD + k0 + kq * 4);
        }
    };
    auto w_sts = [&](int buf) {
#pragma unroll
        for (int i = 0; i < 2; ++i) {
            int idx = t + 128 * i;
            int n = idx >> 3, kq = idx & 7;
            uint4 u;
            u.x = rna(wR[i].x); u.y = rna(wR[i].y);
            u.z = rna(wR[i].z); u.w = rna(wR[i].w);
            *(uint4*)&Ws[buf * LL * APD + n * APD + kq * 4] = u;
        }
    };

    a_issue(0); a_issue(1); a_issue(2);
    w_ldg(0); w_sts(0); w_ldg(1);

    float acc[4][4];
#pragma unroll
    for (int nf = 0; nf < 4; ++nf)
#pragma unroll
        for (int i = 0; i < 4; ++i) acc[nf][i] = 0.0f;

    const int rA0 = (16 * w + g) * APD;
    const int rA1 = (16 * w + g + 8) * APD;

    for (int it = 0; it < NT; ++it) {
        if (it <= NT - 3)
            asm volatile("cp.async.wait_group 2;" ::: "memory");
        else if (it == NT - 2)
            asm volatile("cp.async.wait_group 1;" ::: "memory");
        else
            asm volatile("cp.async.wait_group 0;" ::: "memory");
        __syncthreads();

        const float*    as = As + (it & (NSTG - 1)) * 64 * APD;
        const uint32_t* ws = Ws + (it & 1) * LL * APD;
#pragma unroll
        for (int ks = 0; ks < 4; ++ks) {
            const int k = 8 * ks;
            uint32_t a0 = __float_as_uint(as[rA0 + k + tig]);
            uint32_t a1 = __float_as_uint(as[rA1 + k + tig]);
            uint32_t a2 = __float_as_uint(as[rA0 + k + tig + 4]);
            uint32_t a3 = __float_as_uint(as[rA1 + k + tig + 4]);
#pragma unroll
            for (int nf = 0; nf < 4; ++nf) {
                uint32_t b0 = ws[(8 * nf + g) * APD + k + tig];
                uint32_t b1 = ws[(8 * nf + g) * APD + k + tig + 4];
                mma_tf32(acc[nf], a0, a1, a2, a3, b0, b1);
            }
        }
        if (it + 1 < NT) {
            w_sts((it + 1) & 1);
            if (it + 2 < NT) w_ldg(it + 2);
            if (it + 3 < NT) a_issue(it + 3);
        }
    }

    // ---- epilogue: q = exp(acc + bias) -> qs (smem only) ----
    const int r0l = 16 * w + g;
#pragma unroll
    for (int nf = 0; nf < 4; ++nf) {
        const int n = nf * 8 + 2 * tig;
        float b0 = bs[n], b1 = bs[n + 1];
        float2 v0, v1;
        v0.x = __expf(acc[nf][0] + b0);
        v0.y = __expf(acc[nf][1] + b1);
        v1.x = __expf(acc[nf][2] + b0);
        v1.y = __expf(acc[nf][3] + b1);
        *(float2*)&qs[r0l * 32 + n]       = v0;
        *(float2*)&qs[(r0l + 8) * 32 + n] = v1;
    }
    // Eb[n][k] = bf16(exp(trans[k][n]))
    {
        const int n = t & 31, kb = (t >> 5) * 8;
#pragma unroll
        for (int i = 0; i < 8; ++i) {
            int k = kb + i;
            Eb[n * SPB + k] = __float2bfloat16(__expf(trans[k * 32 + n]));
        }
    }
    if (t < 16)
        ((int4*)ls64)[t] = ((const int4*)(labels + b * TT + blk8 * 64))[t];
    __syncthreads();

    // gold emissions + p0 row
    if (t < 64) {
        int l = ls64[t];
        g_gold[b * TT + blk8 * 64 + t] = __logf(qs[t * 32 + l]);
    }
    if (blk8 == 0 && t < 32) g_p0[b * 32 + t] = qs[t];

    // ------------------ chunk phase: 2 chunks x 2 warp-halves ------------------
    const int ch = w >> 1;
    const int h  = w & 1;
    const int cglob = 2 * blk8 + ch;
    const int ls0 = (cglob == 0) ? 1 : 0;

    __nv_bfloat16* Cc = Cs + ch * 32 * SPB;
    const float* qch = qs + ch * 32 * 32;

    uint32_t Bf[2][4][2];
#pragma unroll
    for (int kc = 0; kc < 2; ++kc)
#pragma unroll
        for (int nt = 0; nt < 4; ++nt) {
            Bf[kc][nt][0] = *(const uint32_t*)&Eb[(8 * nt + g) * SPB + 16 * kc + 2 * tig];
            Bf[kc][nt][1] = *(const uint32_t*)&Eb[(8 * nt + g) * SPB + 16 * kc + 2 * tig + 8];
        }

#pragma unroll
    for (int r = 0; r < 16; ++r) {
        int m = 16 * h + r;
        Cc[m * SPB + lane] = __float2bfloat16(
            __bfloat162float(Eb[lane * SPB + m]) * qch[ls0 * 32 + lane]);
    }
    __syncwarp();

    float xac[4][4];
    float logC = 0.0f;
    const unsigned FULL = 0xffffffffu;

    for (int ls = ls0 + 1; ls < CL; ++ls) {
        uint32_t Af[2][4];
#pragma unroll
        for (int kc = 0; kc < 2; ++kc) {
            const int b0i = (16 * h + g) * SPB + 16 * kc + 2 * tig;
            const int b1i = (16 * h + g + 8) * SPB + 16 * kc + 2 * tig;
            Af[kc][0] = *(const uint32_t*)&Cc[b0i];
            Af[kc][1] = *(const uint32_t*)&Cc[b1i];
            Af[kc][2] = *(const uint32_t*)&Cc[b0i + 8];
            Af[kc][3] = *(const uint32_t*)&Cc[b1i + 8];
        }
#pragma unroll
        for (int nt = 0; nt < 4; ++nt)
#pragma unroll
            for (int v = 0; v < 4; ++v) xac[nt][v] = 0.0f;
#pragma unroll
        for (int kc = 0; kc < 2; ++kc)
#pragma unroll
            for (int nt = 0; nt < 4; ++nt)
                mma_bf16(xac[nt], Af[kc][0], Af[kc][1], Af[kc][2], Af[kc][3],
                         Bf[kc][nt][0], Bf[kc][nt][1]);

#pragma unroll
        for (int nt = 0; nt < 4; ++nt) {
            float2 qv = *(const float2*)&qch[ls * 32 + 8 * nt + 2 * tig];
            xac[nt][0] *= qv.x; xac[nt][1] *= qv.y;
            xac[nt][2] *= qv.x; xac[nt][3] *= qv.y;
        }

        if ((ls & 7) == 7 && ls != CL - 1) {
            float m = xac[0][0];
#pragma unroll
            for (int nt = 0; nt < 4; ++nt)
#pragma unroll
                for (int v = 0; v < 4; ++v) m = fmaxf(m, xac[nt][v]);
#pragma unroll
            for (int o = 16; o; o >>= 1) m = fmaxf(m, __shfl_xor_sync(FULL, m, o));
            float rinv;
            asm("rcp.approx.f32 %0, %1;" : "=f"(rinv) : "f"(m));
            logC += __logf(m);
#pragma unroll
            for (int nt = 0; nt < 4; ++nt)
#pragma unroll
                for (int v = 0; v < 4; ++v) xac[nt][v] *= rinv;
        }

#pragma unroll
        for (int nt = 0; nt < 4; ++nt) {
            uint32_t u01 = bf2pack(xac[nt][1], xac[nt][0]);
            uint32_t u23 = bf2pack(xac[nt][3], xac[nt][2]);
            *(uint32_t*)&Cc[(16 * h + g) * SPB + 8 * nt + 2 * tig]     = u01;
            *(uint32_t*)&Cc[(16 * h + g + 8) * SPB + 8 * nt + 2 * tig] = u23;
        }
        __syncwarp();
    }

    // ---- unify the two halves' scales ----
    {
        float m = xac[0][0];
#pragma unroll
        for (int nt = 0; nt < 4; ++nt)
#pragma unroll
            for (int v = 0; v < 4; ++v) m = fmaxf(m, xac[nt][v]);
#pragma unroll
        for (int o = 16; o; o >>= 1) m = fmaxf(m, __shfl_xor_sync(FULL, m, o));
        float lw = logC + __logf(m);
        if (lane == 0) scl[w] = lw;
    }
    __syncthreads();
    {
        float L = fmaxf(scl[2 * ch], scl[2 * ch + 1]);
        float factor = __expf(logC - L);
#pragma unroll
        for (int nt = 0; nt < 4; ++nt) {
            uint32_t u01 = bf2pack(xac[nt][1] * factor, xac[nt][0] * factor);
            uint32_t u23 = bf2pack(xac[nt][3] * factor, xac[nt][2] * factor);
            *(uint32_t*)&Cc[(16 * h + g) * SPB + 8 * nt + 2 * tig]     = u01;
            *(uint32_t*)&Cc[(16 * h + g + 8) * SPB + 8 * nt + 2 * tig] = u23;
        }
        if (h == 0 && lane == 0) g_cex[b * CH + cglob] = L;
    }
    __syncthreads();

    // cooperative writeout as bf16 pairs: g_cm[(b*CH+c)*512 + r*16 + ip]
    //   = {stored[r][2ip], stored[r][2ip+1]},  stored[r][i] = Cs[i*SPB + r]
    {
        uint32_t* out0 = g_cm + ((size_t)b * CH + 2 * blk8) * 512;
        for (int idx = t; idx < 1024; idx += 128) {
            int c2 = idx >> 9, rem = idx & 511;
            int r = rem >> 4, ip = rem & 15;
            const __nv_bfloat16* base = Cs + c2 * 32 * SPB;
            uint32_t lo = *(const uint16_t*)&base[(2 * ip) * SPB + r];
            uint32_t hi = *(const uint16_t*)&base[(2 * ip + 1) * SPB + r];
            out0[c2 * 512 + r * 16 + ip] = lo | (hi << 16);
        }
    }
}

// ---------------------------------------------------------------------------
// Kernel 2: per-sequence combine + fused finalize.
// Warp 0: p0 -> 16 chunk matvecs, rows prefetched from g_cm (bf16, register
// double-buffered), p broadcast via smem LDS.64 + fma2. Renorm every 4 chunks.
// Warps 1-3: numerator = coalesced g_gold sum + trans-table lookups.
// ---------------------------------------------------------------------------
__global__ void __launch_bounds__(128) crf_combine(const float* __restrict__ start_t,
                                                   const float* __restrict__ end_t,
                                                   const float* __restrict__ trans,
                                                   const int* __restrict__ labels,
                                                   float* __restrict__ out) {
    __shared__ __align__(16) float Ts[LL * LL];
    __shared__ __align__(16) int   Ls[TT];
    __shared__ __align__(8)  float pb[2][32];
    __shared__ float res[4];
    __shared__ bool amLast;

    const int b = blockIdx.x;
    const int t = threadIdx.x;
    const int w = t >> 5;
    const int j = t & 31;
    const unsigned FULL = 0xffffffffu;

    {
        ((float4*)Ts)[t]       = ((const float4*)trans)[t];
        ((float4*)Ts)[t + 128] = ((const float4*)trans)[t + 128];
        ((int4*)Ls)[t] = ((const int4*)(labels + b * TT))[t];
    }
    __syncthreads();

    if (w == 0) {
        const float Eend = __expf(end_t[j]);
        float p = __expf(start_t[j]) * g_p0[b * 32 + j];

        float logC = (j < CH) ? g_cex[b * CH + j] : 0.0f;
#pragma unroll
        for (int o = 16; o; o >>= 1) logC += __shfl_xor_sync(FULL, logC, o);

        const uint32_t* cmb = g_cm + (size_t)b * CH * 512;
        uint4 cur[4], nxt[4];
#pragma unroll
        for (int q = 0; q < 4; ++q)
            cur[q] = ((const uint4*)(cmb + j * 16))[q];

        pb[0][j] = p;
        __syncwarp(FULL);

        float pn = p;
#pragma unroll 1
        for (int c = 0; c < CH; ++c) {
            if (c + 1 < CH) {
                const uint4* np = (const uint4*)(cmb + (c + 1) * 512 + j * 16);
#pragma unroll
                for (int q = 0; q < 4; ++q) nxt[q] = np[q];
            }
            const unsigned long long* pu =
                (const unsigned long long*)&pb[c & 1][0];
            const uint32_t* cw = (const uint32_t*)cur;
            unsigned long long s0 = 0ull, s1 = 0ull, s2 = 0ull, s3 = 0ull;
#pragma unroll
            for (int k = 0; k < 16; ++k) {
                __nv_bfloat162 bb = *(const __nv_bfloat162*)&cw[k];
                float2 cf = __bfloat1622float2(bb);
                unsigned long long cp = pack2(cf.x, cf.y);
                switch (k & 3) {
                    case 0: fma2(s0, pu[k], cp); break;
                    case 1: fma2(s1, pu[k], cp); break;
                    case 2: fma2(s2, pu[k], cp); break;
                    default: fma2(s3, pu[k], cp); break;
                }
            }
            float2 sf = unpack2(add2(add2(s0, s1), add2(s2, s3)));
            pn = sf.x + sf.y;

            if ((c & 3) == 3) {      // renorm every 4 chunks (incl. final)
                float m = pn;
#pragma unroll
                for (int o = 16; o; o >>= 1)
                    m = fmaxf(m, __shfl_xor_sync(FULL, m, o));
                float rinv;
                asm("rcp.approx.f32 %0, %1;" : "=f"(rinv) : "f"(m));
                logC += __logf(m);
                pn *= rinv;
            }
            pb[(c + 1) & 1][j] = pn;
            __syncwarp(FULL);
#pragma unroll
            for (int q = 0; q < 4; ++q) cur[q] = nxt[q];
        }

        float v = pn * Eend;
#pragma unroll
        for (int o = 16; o; o >>= 1) v += __shfl_xor_sync(FULL, v, o);
        if (j == 0) res[0] = logC + __logf(v);
    } else {
        // numerator: coalesced gold-emission sum + trans terms
        const int gi = (w - 1) * 32 + j;     // 0..95
        float acc = 0.0f;
        for (int tt = gi; tt < TT; tt += 96)
            acc += g_gold[b * TT + tt];
        for (int tt = 1 + gi; tt < TT; tt += 96)
            acc += Ts[Ls[tt - 1] * LL + Ls[tt]];
#pragma unroll
        for (int o = 16; o; o >>= 1) acc += __shfl_xor_sync(FULL, acc, o);
        if (j == 0) res[w] = acc;
    }
    __syncthreads();

    if (t == 0) {
        float num = res[1] + res[2] + res[3]
                  + start_t[Ls[0]] + end_t[Ls[TT - 1]];
        g_nll[b] = res[0] - num;
        __threadfence();
        unsigned old = atomicAdd(&g_done, 1u);
        amLast = (old == BB - 1);
    }
    __syncthreads();

    if (amLast && w == 0) {          // fused finalize (deterministic tree)
        __threadfence();
        float v = g_nll[j] + g_nll[j + 32];
#pragma unroll
        for (int o = 16; o; o >>= 1) v += __shfl_xor_sync(FULL, v, o);
        if (j == 0) out[0] = v * (1.0f / (float)BB);
    }
}

// ---------------------------------------------------------------------------
extern "C" void kernel_launch(void* const* d_in, const int* in_sizes, int n_in,
                              void* d_out, int out_size) {
    const float* emb    = (const float*)d_in[0];
    const float* W      = (const float*)d_in[1];
    const float* bias   = (const float*)d_in[2];
    const float* startt = (const float*)d_in[3];
    const float* endt   = (const float*)d_in[4];
    const float* trans  = (const float*)d_in[5];
    const int*   labels = (const int*)d_in[6];

    static int attr_set = 0;
    if (!attr_set) {
        cudaFuncSetAttribute(emis_fused, cudaFuncAttributeMaxDynamicSharedMemorySize,
                             SM_TOTAL);
        attr_set = 1;
    }

    emis_fused<<<(BB * TT) / 64, 128, SM_TOTAL>>>(emb, W, bias, trans, labels);
    crf_combine<<<BB, 128>>>(startt, endt, trans, labels, (float*)d_out);
}

// round 13
// speedup vs baseline: 1.2366x; 1.0585x over previous
#include <cuda_runtime.h>
#include <cuda_bf16.h>
#include <cstdint>

#define BB 64
#define TT 512
#define DD 1024
#define LL 32
#define CH 16    // chunks per sequence
#define CL 32    // steps per chunk

__device__ __align__(16) uint32_t g_cm[BB * CH * 512];  // 2 MB: chunk mats, bf16x2
__device__ float g_cex[BB * CH];             // chunk log-scales
__device__ float g_gold[BB * TT];            // log q[t, label_t]
__device__ float g_p0[BB * LL];              // q row 0 per sequence
__device__ float g_nll[BB];
__device__ unsigned g_seqdone[BB];           // per-sequence block counters (self-resetting)
__device__ unsigned g_done;                  // sequence-combine counter (self-resetting)

// ---------------------------------------------------------------------------
// helpers
// ---------------------------------------------------------------------------
__device__ __forceinline__ uint32_t rna(float x) {   // unbiased round to tf32
    uint32_t r;
    asm("cvt.rna.tf32.f32 %0, %1;" : "=r"(r) : "f"(x));
    return r;
}
__device__ __forceinline__ void mma_tf32(float* c,
                                         uint32_t a0, uint32_t a1,
                                         uint32_t a2, uint32_t a3,
                                         uint32_t b0, uint32_t b1) {
    asm volatile(
        "mma.sync.aligned.m16n8k8.row.col.f32.tf32.tf32.f32 "
        "{%0,%1,%2,%3}, {%4,%5,%6,%7}, {%8,%9}, {%0,%1,%2,%3};"
        : "+f"(c[0]), "+f"(c[1]), "+f"(c[2]), "+f"(c[3])
        : "r"(a0), "r"(a1), "r"(a2), "r"(a3), "r"(b0), "r"(b1));
}
__device__ __forceinline__ void mma_bf16(float* c,
                                         uint32_t a0, uint32_t a1,
                                         uint32_t a2, uint32_t a3,
                                         uint32_t b0, uint32_t b1) {
    asm volatile(
        "mma.sync.aligned.m16n8k16.row.col.f32.bf16.bf16.f32 "
        "{%0,%1,%2,%3}, {%4,%5,%6,%7}, {%8,%9}, {%0,%1,%2,%3};"
        : "+f"(c[0]), "+f"(c[1]), "+f"(c[2]), "+f"(c[3])
        : "r"(a0), "r"(a1), "r"(a2), "r"(a3), "r"(b0), "r"(b1));
}
__device__ __forceinline__ uint32_t bf2pack(float hi, float lo) {
    uint32_t r;
    asm("cvt.rn.bf16x2.f32 %0, %1, %2;" : "=r"(r) : "f"(hi), "f"(lo));
    return r;
}
__device__ __forceinline__ void fma2(unsigned long long& d, unsigned long long a,
                                     unsigned long long b) {
    asm("fma.rn.f32x2 %0, %1, %2, %0;" : "+l"(d) : "l"(a), "l"(b));
}
__device__ __forceinline__ unsigned long long add2(unsigned long long a,
                                                   unsigned long long b) {
    unsigned long long r;
    asm("add.rn.f32x2 %0, %1, %2;" : "=l"(r) : "l"(a), "l"(b));
    return r;
}
__device__ __forceinline__ unsigned long long pack2(float lo, float hi) {
    unsigned long long r;
    asm("mov.b64 %0, {%1, %2};" : "=l"(r) : "f"(lo), "f"(hi));
    return r;
}
__device__ __forceinline__ float2 unpack2(unsigned long long v) {
    float2 f;
    asm("mov.b64 {%0, %1}, %2;" : "=f"(f.x), "=f"(f.y) : "l"(v));
    return f;
}

// ---------------------------------------------------------------------------
// Single fused kernel: emissions GEMM (tf32 mma, cp.async pipeline)
//   + chunk matrix products (bf16 mma) on the block's 64 rows (= 2 chunks)
//   + per-sequence combine (last-of-8-blocks pattern)
//   + global mean (last-of-64-combiners pattern).
//
// dynamic smem layout (bytes):
//   [0, 36864)      As[4][64*APD] f32 (GEMM stage buffers)
//     -- chunk-phase aliases (stages dead after mainloop):
//     [0, 8192)       qs [64][32] f32
//     [8192, 10752)   Eb bf16 [32][SPB]
//     [10752, 15872)  Cs bf16 [2][32][SPB]
//     [15872, 15904)  scl[8] f32
//     [15904, 16160)  ls64[64] int
//     -- combine-phase aliases (qs dead after chunk phase):
//     [0, 4096)       Ts f32 [32][32]
//     [4096, 6144)    Ls int [512]
//     [6144, 6400)    pb f32 [2][32]
//     [6400, 6416)    res f32 [4]
//   [36864, 46080)  Ws[2][32*APD] u32 (tf32 bits)
//   [46080, 46208)  bs[32] f32
// ---------------------------------------------------------------------------
#define NSTG 4
#define APD  36
#define NT   (DD / 32)
#define SPB  40
#define SM_TOTAL 46208

__global__ void __launch_bounds__(128) emis_fused(const float* __restrict__ A,
                                                  const float* __restrict__ W,
                                                  const float* __restrict__ bias,
                                                  const float* __restrict__ trans,
                                                  const int* __restrict__ labels,
                                                  const float* __restrict__ start_t,
                                                  const float* __restrict__ end_t,
                                                  float* __restrict__ out) {
    extern __shared__ __align__(16) char smraw[];
    float*    As = (float*)smraw;
    uint32_t* Ws = (uint32_t*)(smraw + 36864);
    float*    bs = (float*)(smraw + 46080);
    // chunk-phase aliases
    float*         qs   = (float*)smraw;                      // [64][32]
    __nv_bfloat16* Eb   = (__nv_bfloat16*)(smraw + 8192);     // [32][SPB]
    __nv_bfloat16* Cs   = (__nv_bfloat16*)(smraw + 10752);    // [2][32][SPB]
    float*         scl  = (float*)(smraw + 15872);            // [8]
    int*           ls64 = (int*)(smraw + 15904);              // [64]
    // combine-phase aliases
    float* Ts  = (float*)smraw;                               // [32][32]
    int*   Ls  = (int*)(smraw + 4096);                        // [512]
    float* pb  = (float*)(smraw + 6144);                      // [2][32]
    float* res = (float*)(smraw + 6400);                      // [4]

    const int t    = threadIdx.x;
    const int w    = t >> 5;
    const int lane = t & 31;
    const int g    = lane >> 2;
    const int tig  = lane & 3;
    const int row0 = blockIdx.x * 64;
    const int b    = blockIdx.x >> 3;
    const int blk8 = blockIdx.x & 7;
    const unsigned FULL = 0xffffffffu;

    if (t < LL) bs[t] = bias[t];

    // ------------------ GEMM phase (proven pipeline) ------------------
    auto a_issue = [&](int tile) {
        const int s = tile & (NSTG - 1);
        const int k0 = tile * 32;
#pragma unroll
        for (int i = 0; i < 4; ++i) {
            int idx = t + 128 * i;
            int m = idx >> 3, kq = idx & 7;
            uint32_t dst = (uint32_t)__cvta_generic_to_shared(
                &As[s * 64 * APD + m * APD + kq * 4]);
            const float* src = A + (size_t)(row0 + m) * DD + k0 + kq * 4;
            asm volatile("cp.async.cg.shared.global [%0], [%1], 16;"
                         :: "r"(dst), "l"(src));
        }
        asm volatile("cp.async.commit_group;" ::: "memory");
    };

    float4 wR[2];
    auto w_ldg = [&](int tile) {
        const int k0 = tile * 32;
#pragma unroll
        for (int i = 0; i < 2; ++i) {
            int idx = t + 128 * i;
            int n = idx >> 3, kq = idx & 7;
            wR[i] = *(const float4*)(W + (size_t)n * DD + k0 + kq * 4);
        }
    };
    auto w_sts = [&](int buf) {
#pragma unroll
        for (int i = 0; i < 2; ++i) {
            int idx = t + 128 * i;
            int n = idx >> 3, kq = idx & 7;
            uint4 u;
            u.x = rna(wR[i].x); u.y = rna(wR[i].y);
            u.z = rna(wR[i].z); u.w = rna(wR[i].w);
            *(uint4*)&Ws[buf * LL * APD + n * APD + kq * 4] = u;
        }
    };

    a_issue(0); a_issue(1); a_issue(2);
    w_ldg(0); w_sts(0); w_ldg(1);

    float acc[4][4];
#pragma unroll
    for (int nf = 0; nf < 4; ++nf)
#pragma unroll
        for (int i = 0; i < 4; ++i) acc[nf][i] = 0.0f;

    const int rA0 = (16 * w + g) * APD;
    const int rA1 = (16 * w + g + 8) * APD;

    for (int it = 0; it < NT; ++it) {
        if (it <= NT - 3)
            asm volatile("cp.async.wait_group 2;" ::: "memory");
        else if (it == NT - 2)
            asm volatile("cp.async.wait_group 1;" ::: "memory");
        else
            asm volatile("cp.async.wait_group 0;" ::: "memory");
        __syncthreads();

        const float*    as = As + (it & (NSTG - 1)) * 64 * APD;
        const uint32_t* ws = Ws + (it & 1) * LL * APD;
#pragma unroll
        for (int ks = 0; ks < 4; ++ks) {
            const int k = 8 * ks;
            uint32_t a0 = __float_as_uint(as[rA0 + k + tig]);
            uint32_t a1 = __float_as_uint(as[rA1 + k + tig]);
            uint32_t a2 = __float_as_uint(as[rA0 + k + tig + 4]);
            uint32_t a3 = __float_as_uint(as[rA1 + k + tig + 4]);
#pragma unroll
            for (int nf = 0; nf < 4; ++nf) {
                uint32_t b0 = ws[(8 * nf + g) * APD + k + tig];
                uint32_t b1 = ws[(8 * nf + g) * APD + k + tig + 4];
                mma_tf32(acc[nf], a0, a1, a2, a3, b0, b1);
            }
        }
        if (it + 1 < NT) {
            w_sts((it + 1) & 1);
            if (it + 2 < NT) w_ldg(it + 2);
            if (it + 3 < NT) a_issue(it + 3);
        }
    }

    // ---- epilogue: q = exp(acc + bias) -> qs (smem only) ----
    const int r0l = 16 * w + g;
#pragma unroll
    for (int nf = 0; nf < 4; ++nf) {
        const int n = nf * 8 + 2 * tig;
        float b0 = bs[n], b1 = bs[n + 1];
        float2 v0, v1;
        v0.x = __expf(acc[nf][0] + b0);
        v0.y = __expf(acc[nf][1] + b1);
        v1.x = __expf(acc[nf][2] + b0);
        v1.y = __expf(acc[nf][3] + b1);
        *(float2*)&qs[r0l * 32 + n]       = v0;
        *(float2*)&qs[(r0l + 8) * 32 + n] = v1;
    }
    // Eb[n][k] = bf16(exp(trans[k][n]))
    {
        const int n = t & 31, kb = (t >> 5) * 8;
#pragma unroll
        for (int i = 0; i < 8; ++i) {
            int k = kb + i;
            Eb[n * SPB + k] = __float2bfloat16(__expf(trans[k * 32 + n]));
        }
    }
    if (t < 16)
        ((int4*)ls64)[t] = ((const int4*)(labels + b * TT + blk8 * 64))[t];
    __syncthreads();

    // gold emissions + p0 row
    if (t < 64) {
        int l = ls64[t];
        g_gold[b * TT + blk8 * 64 + t] = __logf(qs[t * 32 + l]);
    }
    if (blk8 == 0 && t < 32) g_p0[b * 32 + t] = qs[t];

    // ------------------ chunk phase: 2 chunks x 2 warp-halves ------------------
    const int ch = w >> 1;
    const int h  = w & 1;
    const int cglob = 2 * blk8 + ch;
    const int ls0 = (cglob == 0) ? 1 : 0;

    __nv_bfloat16* Cc = Cs + ch * 32 * SPB;
    const float* qch = qs + ch * 32 * 32;

    uint32_t Bf[2][4][2];
#pragma unroll
    for (int kc = 0; kc < 2; ++kc)
#pragma unroll
        for (int nt = 0; nt < 4; ++nt) {
            Bf[kc][nt][0] = *(const uint32_t*)&Eb[(8 * nt + g) * SPB + 16 * kc + 2 * tig];
            Bf[kc][nt][1] = *(const uint32_t*)&Eb[(8 * nt + g) * SPB + 16 * kc + 2 * tig + 8];
        }

#pragma unroll
    for (int r = 0; r < 16; ++r) {
        int m = 16 * h + r;
        Cc[m * SPB + lane] = __float2bfloat16(
            __bfloat162float(Eb[lane * SPB + m]) * qch[ls0 * 32 + lane]);
    }
    __syncwarp();

    float xac[4][4];
    float logC = 0.0f;

    for (int ls = ls0 + 1; ls < CL; ++ls) {
        uint32_t Af[2][4];
#pragma unroll
        for (int kc = 0; kc < 2; ++kc) {
            const int b0i = (16 * h + g) * SPB + 16 * kc + 2 * tig;
            const int b1i = (16 * h + g + 8) * SPB + 16 * kc + 2 * tig;
            Af[kc][0] = *(const uint32_t*)&Cc[b0i];
            Af[kc][1] = *(const uint32_t*)&Cc[b1i];
            Af[kc][2] = *(const uint32_t*)&Cc[b0i + 8];
            Af[kc][3] = *(const uint32_t*)&Cc[b1i + 8];
        }
#pragma unroll
        for (int nt = 0; nt < 4; ++nt)
#pragma unroll
            for (int v = 0; v < 4; ++v) xac[nt][v] = 0.0f;
#pragma unroll
        for (int kc = 0; kc < 2; ++kc)
#pragma unroll
            for (int nt = 0; nt < 4; ++nt)
                mma_bf16(xac[nt], Af[kc][0], Af[kc][1], Af[kc][2], Af[kc][3],
                         Bf[kc][nt][0], Bf[kc][nt][1]);

#pragma unroll
        for (int nt = 0; nt < 4; ++nt) {
            float2 qv = *(const float2*)&qch[ls * 32 + 8 * nt + 2 * tig];
            xac[nt][0] *= qv.x; xac[nt][1] *= qv.y;
            xac[nt][2] *= qv.x; xac[nt][3] *= qv.y;
        }

        if ((ls & 7) == 7 && ls != CL - 1) {
            float m = xac[0][0];
#pragma unroll
            for (int nt = 0; nt < 4; ++nt)
#pragma unroll
                for (int v = 0; v < 4; ++v) m = fmaxf(m, xac[nt][v]);
#pragma unroll
            for (int o = 16; o; o >>= 1) m = fmaxf(m, __shfl_xor_sync(FULL, m, o));
            float rinv;
            asm("rcp.approx.f32 %0, %1;" : "=f"(rinv) : "f"(m));
            logC += __logf(m);
#pragma unroll
            for (int nt = 0; nt < 4; ++nt)
#pragma unroll
                for (int v = 0; v < 4; ++v) xac[nt][v] *= rinv;
        }

#pragma unroll
        for (int nt = 0; nt < 4; ++nt) {
            uint32_t u01 = bf2pack(xac[nt][1], xac[nt][0]);
            uint32_t u23 = bf2pack(xac[nt][3], xac[nt][2]);
            *(uint32_t*)&Cc[(16 * h + g) * SPB + 8 * nt + 2 * tig]     = u01;
            *(uint32_t*)&Cc[(16 * h + g + 8) * SPB + 8 * nt + 2 * tig] = u23;
        }
        __syncwarp();
    }

    // ---- unify the two halves' scales ----
    {
        float m = xac[0][0];
#pragma unroll
        for (int nt = 0; nt < 4; ++nt)
#pragma unroll
            for (int v = 0; v < 4; ++v) m = fmaxf(m, xac[nt][v]);
#pragma unroll
        for (int o = 16; o; o >>= 1) m = fmaxf(m, __shfl_xor_sync(FULL, m, o));
        float lw = logC + __logf(m);
        if (lane == 0) scl[w] = lw;
    }
    __syncthreads();
    {
        float L = fmaxf(scl[2 * ch], scl[2 * ch + 1]);
        float factor = __expf(logC - L);
#pragma unroll
        for (int nt = 0; nt < 4; ++nt) {
            uint32_t u01 = bf2pack(xac[nt][1] * factor, xac[nt][0] * factor);
            uint32_t u23 = bf2pack(xac[nt][3] * factor, xac[nt][2] * factor);
            *(uint32_t*)&Cc[(16 * h + g) * SPB + 8 * nt + 2 * tig]     = u01;
            *(uint32_t*)&Cc[(16 * h + g + 8) * SPB + 8 * nt + 2 * tig] = u23;
        }
        if (h == 0 && lane == 0) g_cex[b * CH + cglob] = L;
    }
    __syncthreads();

    // cooperative writeout as bf16 pairs
    {
        uint32_t* out0 = g_cm + ((size_t)b * CH + 2 * blk8) * 512;
        for (int idx = t; idx < 1024; idx += 128) {
            int c2 = idx >> 9, rem = idx & 511;
            int r = rem >> 4, ip = rem & 15;
            const __nv_bfloat16* base = Cs + c2 * 32 * SPB;
            uint32_t lo = *(const uint16_t*)&base[(2 * ip) * SPB + r];
            uint32_t hi = *(const uint16_t*)&base[(2 * ip + 1) * SPB + r];
            out0[c2 * 512 + r * 16 + ip] = lo | (hi << 16);
        }
    }
    __syncthreads();

    // ------------------ per-sequence combine: last of 8 blocks ------------------
    __shared__ bool amLastSeq;
    if (t == 0) {
        __threadfence();
        unsigned old = atomicAdd(&g_seqdone[b], 1u);
        amLastSeq = (old == 7u);
    }
    __syncthreads();
    if (!amLastSeq) return;
    __threadfence();
    if (t == 0) g_seqdone[b] = 0;       // reset for next graph replay

    // stage trans + labels into freed smem
    ((float4*)Ts)[t * 2]     = ((const float4*)trans)[t * 2];
    ((float4*)Ts)[t * 2 + 1] = ((const float4*)trans)[t * 2 + 1];
    ((int4*)Ls)[t] = ((const int4*)(labels + b * TT))[t];
    __syncthreads();

    if (w == 0) {
        const int j = lane;
        const float Eend = __expf(end_t[j]);
        float p = __expf(start_t[j]) * g_p0[b * 32 + j];

        float logCc = (j < CH) ? g_cex[b * CH + j] : 0.0f;
#pragma unroll
        for (int o = 16; o; o >>= 1) logCc += __shfl_xor_sync(FULL, logCc, o);

        const uint32_t* cmb = g_cm + (size_t)b * CH * 512;
        uint4 cur[4], nxt[4];
#pragma unroll
        for (int q = 0; q < 4; ++q)
            cur[q] = ((const uint4*)(cmb + j * 16))[q];

        pb[j] = p;
        __syncwarp(FULL);

        float pn = p;
#pragma unroll 1
        for (int c = 0; c < CH; ++c) {
            if (c + 1 < CH) {
                const uint4* np = (const uint4*)(cmb + (c + 1) * 512 + j * 16);
#pragma unroll
                for (int q = 0; q < 4; ++q) nxt[q] = np[q];
            }
            const unsigned long long* pu =
                (const unsigned long long*)&pb[(c & 1) * 32];
            const uint32_t* cw = (const uint32_t*)cur;
            unsigned long long s0 = 0ull, s1 = 0ull, s2 = 0ull, s3 = 0ull;
#pragma unroll
            for (int k = 0; k < 16; ++k) {
                __nv_bfloat162 bb = *(const __nv_bfloat162*)&cw[k];
                float2 cf = __bfloat1622float2(bb);
                unsigned long long cp = pack2(cf.x, cf.y);
                switch (k & 3) {
                    case 0: fma2(s0, pu[k], cp); break;
                    case 1: fma2(s1, pu[k], cp); break;
                    case 2: fma2(s2, pu[k], cp); break;
                    default: fma2(s3, pu[k], cp); break;
                }
            }
            float2 sf = unpack2(add2(add2(s0, s1), add2(s2, s3)));
            pn = sf.x + sf.y;

            if ((c & 3) == 3) {
                float m = pn;
#pragma unroll
                for (int o = 16; o; o >>= 1)
                    m = fmaxf(m, __shfl_xor_sync(FULL, m, o));
                float rinv;
                asm("rcp.approx.f32 %0, %1;" : "=f"(rinv) : "f"(m));
                logCc += __logf(m);
                pn *= rinv;
            }
            pb[((c + 1) & 1) * 32 + j] = pn;
            __syncwarp(FULL);
#pragma unroll
            for (int q = 0; q < 4; ++q) cur[q] = nxt[q];
        }

        float v = pn * Eend;
#pragma unroll
        for (int o = 16; o; o >>= 1) v += __shfl_xor_sync(FULL, v, o);
        if (j == 0) res[0] = logCc + __logf(v);
    } else {
        const int j = lane;
        const int gi = (w - 1) * 32 + j;
        float accn = 0.0f;
        for (int tt = gi; tt < TT; tt += 96)
            accn += g_gold[b * TT + tt];
        for (int tt = 1 + gi; tt < TT; tt += 96)
            accn += Ts[Ls[tt - 1] * LL + Ls[tt]];
#pragma unroll
        for (int o = 16; o; o >>= 1) accn += __shfl_xor_sync(FULL, accn, o);
        if (j == 0) res[w] = accn;
    }
    __syncthreads();

    // ------------------ global finalize: last of 64 combiners ------------------
    __shared__ bool amLast;
    if (t == 0) {
        float num = res[1] + res[2] + res[3]
                  + start_t[Ls[0]] + end_t[Ls[TT - 1]];
        g_nll[b] = res[0] - num;
        __threadfence();
        unsigned old = atomicAdd(&g_done, 1u);
        amLast = (old == BB - 1);
    }
    __syncthreads();

    if (amLast) {
        if (t == 0) g_done = 0;         // reset for next graph replay
        if (w == 0) {
            __threadfence();
            const int j = lane;
            float v = g_nll[j] + g_nll[j + 32];
#pragma unroll
            for (int o = 16; o; o >>= 1) v += __shfl_xor_sync(FULL, v, o);
            if (j == 0) out[0] = v * (1.0f / (float)BB);
        }
    }
}

// ---------------------------------------------------------------------------
extern "C" void kernel_launch(void* const* d_in, const int* in_sizes, int n_in,
                              void* d_out, int out_size) {
    const float* emb    = (const float*)d_in[0];
    const float* W      = (const float*)d_in[1];
    const float* bias   = (const float*)d_in[2];
    const float* startt = (const float*)d_in[3];
    const float* endt   = (const float*)d_in[4];
    const float* trans  = (const float*)d_in[5];
    const int*   labels = (const int*)d_in[6];

    static int attr_set = 0;
    if (!attr_set) {
        cudaFuncSetAttribute(emis_fused, cudaFuncAttributeMaxDynamicSharedMemorySize,
                             SM_TOTAL);
        attr_set = 1;
    }

    emis_fused<<<(BB * TT) / 64, 128, SM_TOTAL>>>(emb, W, bias, trans, labels,
                                                  startt, endt, (float*)d_out);
}